// round 6
// baseline (speedup 1.0000x reference)
#include <cuda_runtime.h>

#define D 64
#define MAX_N 100000
#define MAX_E 1600000
#define ALPHA_LEAKY 0.2f
#define EPS_F 1e-10f

// ---------------- device scratch (no allocations allowed) ----------------
__device__ float    g_vq[D];              // proj_w^T @ wq
__device__ float    g_cq;                 // proj_b . wq
__device__ float    g_sq[MAX_N];          // per-query scalar
__device__ float    g_sk[MAX_N];          // per-key scalar (incl. attend_b)
__device__ float    g_Kp[(size_t)MAX_N * D]; // projected key/value nodes
__device__ unsigned g_emax[MAX_N];        // ordered-uint encoded max
__device__ float    g_esum[MAX_N];
__device__ float    g_e[MAX_E];           // per-edge scratch (e, then e_exp)
__device__ int      g_qi[MAX_E];          // decoded int32 edge endpoints
__device__ int      g_ki[MAX_E];
__device__ int      g_is64;               // 1 if edge_index buffer is int64

// ordered-uint mapping for float atomicMax (handles negatives)
__device__ __forceinline__ unsigned fmap(float f) {
    unsigned b = __float_as_uint(f);
    return (b & 0x80000000u) ? ~b : (b | 0x80000000u);
}
__device__ __forceinline__ float funmap(unsigned u) {
    unsigned b = (u & 0x80000000u) ? (u ^ 0x80000000u) : ~u;
    return __uint_as_float(b);
}

// ---------------- K-1: detect edge_index dtype ---------------------------
// Interpret entries at the start of BOTH rows as int64. For a true int64
// buffer every sampled value lies in [0, N). For an int32 buffer the int64
// view fuses adjacent indices (lo + hi*2^32), which blows out of range
// unless hi happens to be 0 (p ~ 1e-5 per sample; AND over 512 samples).
__global__ void k_detect(const void* __restrict__ ei, int E, int N) {
    __shared__ int ok_s;
    if (threadIdx.x == 0) ok_s = 1;
    __syncthreads();
    const long long* p = (const long long*)ei;
    int i = threadIdx.x;
    int bad = 0;
    if (i < E) {
        long long v = p[i];                 // row 0 sample (in-bounds both dtypes)
        if (v < 0 || v >= (long long)N) bad = 1;
        // row-1 sample: offset E int64s if true int64, E/2 int64s if int32.
        // Use E/2 int64 offset (= E int32s): in-bounds for BOTH dtypes, and
        // for int32 data this lands inside row 0/1 index data either way.
        long long w = p[(size_t)(E / 2) + i];
        if (w < 0 || w >= (long long)N) bad = 1;
    }
    if (bad) atomicAnd(&ok_s, 0);
    __syncthreads();
    if (threadIdx.x == 0) g_is64 = ok_s;
}

// ---------------- K0: fold attention weights through projection ----------
__global__ void k_fold(const float* __restrict__ pw,
                       const float* __restrict__ pb,
                       const float* __restrict__ aw) {
    int j = threadIdx.x;  // 0..63
    float vq = 0.f;
    for (int d = 0; d < D; d++) vq += aw[d] * pw[d * D + j];
    g_vq[j] = vq;
    if (j == 0) {
        float cq = 0.f;
        for (int d = 0; d < D; d++) cq += pb[d] * aw[d];
        g_cq = cq;
    }
}

// ---------------- K1: Kp = kv @ W^T + b  (64-node tiles, 4x4 reg tiling) --
__global__ __launch_bounds__(256) void k_proj(const float* __restrict__ kv,
                                              const float* __restrict__ pw,
                                              const float* __restrict__ pb,
                                              int N) {
    __shared__ float pw_s[D * 65];
    __shared__ float kv_s[64 * 65];
    __shared__ float pb_s[D];
    int tid = threadIdx.x;
    int n0 = blockIdx.x * 64;

    for (int i = tid; i < D * D; i += 256) {
        int r = i >> 6, c = i & 63;
        pw_s[r * 65 + c] = pw[i];
    }
    if (tid < D) pb_s[tid] = pb[tid];
    for (int i = tid; i < 64 * D; i += 256) {
        int r = i >> 6, c = i & 63;
        int n = n0 + r;
        kv_s[r * 65 + c] = (n < N) ? kv[(size_t)n * D + c] : 0.f;
    }
    __syncthreads();

    int tx = tid & 15;   // d-tile
    int ty = tid >> 4;   // node-tile
    float acc[4][4] = {};
#pragma unroll
    for (int j = 0; j < D; j++) {
        float a[4], b[4];
#pragma unroll
        for (int r = 0; r < 4; r++) a[r] = kv_s[(ty * 4 + r) * 65 + j];
#pragma unroll
        for (int c = 0; c < 4; c++) b[c] = pw_s[(tx * 4 + c) * 65 + j];
#pragma unroll
        for (int r = 0; r < 4; r++)
#pragma unroll
            for (int c = 0; c < 4; c++) acc[r][c] += a[r] * b[c];
    }
#pragma unroll
    for (int r = 0; r < 4; r++) {
        int n = n0 + ty * 4 + r;
        if (n < N) {
#pragma unroll
            for (int c = 0; c < 4; c++)
                g_Kp[(size_t)n * D + tx * 4 + c] = acc[r][c] + pb_s[tx * 4 + c];
        }
    }
}

// ---------------- K2: per-node scalars sq, sk (one warp per node) --------
__global__ __launch_bounds__(256) void k_scal(const float* __restrict__ q,
                                              const float* __restrict__ aw,
                                              const float* __restrict__ ab,
                                              int Nq, int Nk) {
    __shared__ float vq_s[D], wk_s[D];
    int tid = threadIdx.x;
    if (tid < D) {
        vq_s[tid] = g_vq[tid];
        wk_s[tid] = aw[D + tid];
    }
    __syncthreads();
    int warp = tid >> 5, lane = tid & 31;
    int n = blockIdx.x * 8 + warp;
    float b0 = ab[0];
    if (n < Nq) {
        float2 x = ((const float2*)(q + (size_t)n * D))[lane];
        float s = x.x * vq_s[2 * lane] + x.y * vq_s[2 * lane + 1];
#pragma unroll
        for (int o = 16; o; o >>= 1) s += __shfl_xor_sync(0xFFFFFFFFu, s, o);
        if (lane == 0) g_sq[n] = s + g_cq;
    }
    if (n < Nk) {
        float2 x = ((const float2*)(g_Kp + (size_t)n * D))[lane];
        float s = x.x * wk_s[2 * lane] + x.y * wk_s[2 * lane + 1];
#pragma unroll
        for (int o = 16; o; o >>= 1) s += __shfl_xor_sync(0xFFFFFFFFu, s, o);
        if (lane == 0) g_sk[n] = s + b0;  // attend_b folded here
    }
}

// ---------------- K3: re-init accumulators (runs every graph replay) -----
__global__ void k_init(float* __restrict__ out, int Nq, int out_n) {
    int total = out_n > Nq ? out_n : Nq;
    for (int i = blockIdx.x * blockDim.x + threadIdx.x; i < total;
         i += gridDim.x * blockDim.x) {
        if (i < out_n) out[i] = 0.f;
        if (i < Nq) {
            g_emax[i] = 0u;        // maps below every finite float
            g_esum[i] = 0.f;
        }
    }
}

// ---------------- K4: edge pass 1 — decode indices, e, segment max -------
__global__ __launch_bounds__(256) void k_edge1(const void* __restrict__ ei,
                                               int E, int Nq, int Nk) {
    int e = blockIdx.x * 256 + threadIdx.x;
    if (e >= E) return;
    int qi, ki;
    if (g_is64) {   // uniform branch
        const long long* p = (const long long*)ei;
        qi = (int)p[e];
        ki = (int)p[(size_t)E + e];
    } else {
        const int* p = (const int*)ei;
        qi = p[e];
        ki = p[(size_t)E + e];
    }
    // defensive clamp: wrong dtype guess yields wrong numbers, never a crash
    if ((unsigned)qi >= (unsigned)Nq) qi = 0;
    if ((unsigned)ki >= (unsigned)Nk) ki = 0;
    g_qi[e] = qi;
    g_ki[e] = ki;
    float s = g_sq[qi] + g_sk[ki];
    s = (s > 0.f) ? s : ALPHA_LEAKY * s;
    g_e[e] = s;
    atomicMax(&g_emax[qi], fmap(s));
}

// ---------------- K5: edge pass 2 — exp + segment sum --------------------
__global__ __launch_bounds__(256) void k_edge2(int E) {
    int e = blockIdx.x * 256 + threadIdx.x;
    if (e >= E) return;
    int qi = g_qi[e];
    float mx = funmap(g_emax[qi]);
    float ex = __expf(g_e[e] - mx);
    g_e[e] = ex;
    atomicAdd(&g_esum[qi], ex);
}

// ---------------- K6: edge pass 3 — weighted aggregation -----------------
// 16 lanes per edge: each lane handles one float4 (coalesced 256B gather of
// the Kp row, then a single vector red per lane into out[qi]).
__global__ __launch_bounds__(256) void k_edge3(float* __restrict__ out, int E) {
    int t = blockIdx.x * 256 + threadIdx.x;
    int e = t >> 4;
    int lane = t & 15;
    if (e >= E) return;
    int qi = g_qi[e];
    int ki = g_ki[e];
    float attn = g_e[e] / (g_esum[qi] + EPS_F);
    float4 v = ((const float4*)(g_Kp + (size_t)ki * D))[lane];
    float4 r = make_float4(v.x * attn, v.y * attn, v.z * attn, v.w * attn);
    atomicAdd((float4*)(out + (size_t)qi * D + lane * 4), r);
}

// ---------------- host ----------------------------------------------------
extern "C" void kernel_launch(void* const* d_in, const int* in_sizes, int n_in,
                              void* d_out, int out_size) {
    const float* q  = (const float*)d_in[0];
    const float* kv = (const float*)d_in[1];
    const void*  ei = d_in[2];
    const float* pw = (const float*)d_in[3];
    const float* pb = (const float*)d_in[4];
    const float* aw = (const float*)d_in[5];
    const float* ab = (const float*)d_in[6];
    float* out = (float*)d_out;

    int Nq = in_sizes[0] / D;
    int Nk = in_sizes[1] / D;
    int E  = in_sizes[2] / 2;
    int Nmax = Nq > Nk ? Nq : Nk;

    k_detect<<<1, 256>>>(ei, E, Nq);
    k_fold<<<1, 64>>>(pw, pb, aw);
    k_proj<<<(Nk + 63) / 64, 256>>>(kv, pw, pb, Nk);
    k_scal<<<(Nmax + 7) / 8, 256>>>(q, aw, ab, Nq, Nk);
    k_init<<<592, 256>>>(out, Nq, out_size);
    k_edge1<<<(E + 255) / 256, 256>>>(ei, E, Nq, Nk);
    k_edge2<<<(E + 255) / 256, 256>>>(E);
    k_edge3<<<(E + 15) / 16, 256>>>(out, E);
}